// round 5
// baseline (speedup 1.0000x reference)
#include <cuda_runtime.h>
#include <cuda_bf16.h>
#include <cstdint>
#include <math.h>

#define S 2048
#define D 2048
#define H 16
#define HD 128
#define FFI 8192
#define EPS 1e-5f
#define QKVN 6144            // fused QKV output width
#define W13N 16384           // fused w1|w3 output width

// ---------------------------------------------------------------------------
// Static device scratch
// ---------------------------------------------------------------------------
__device__ float g_qkv[S * QKVN];     // [S, 6144] = Q | K | V
__device__ float g_ao[S * D];
__device__ float g_x1[S * D];
__device__ float g_h13[S * W13N];     // [S, 16384] = h1 | h3

__device__ __nv_bfloat16 g_nx_hi[S * D],  g_nx_lo[S * D];
__device__ __nv_bfloat16 g_ao_hi[S * D],  g_ao_lo[S * D];
__device__ __nv_bfloat16 g_g_hi[S * FFI], g_g_lo[S * FFI];

// packed transposed+split weights, [N, K] bf16
__device__ __nv_bfloat16 g_wqkvT_hi[QKVN * D], g_wqkvT_lo[QKVN * D];
__device__ __nv_bfloat16 g_woT_hi[D * D],      g_woT_lo[D * D];
__device__ __nv_bfloat16 g_w13T_hi[W13N * D],  g_w13T_lo[W13N * D];
__device__ __nv_bfloat16 g_w2T_hi[D * FFI],    g_w2T_lo[D * FFI];

// ---------------------------------------------------------------------------
// PTX helpers (baseline sm_80+, compile for compute_103)
// ---------------------------------------------------------------------------
__device__ __forceinline__ uint32_t smem_u32(const void* p) {
    uint32_t a;
    asm("{ .reg .u64 t; cvta.to.shared.u64 t, %1; cvt.u32.u64 %0, t; }"
        : "=r"(a) : "l"(p));
    return a;
}
#define CP_ASYNC16(dst, src) \
    asm volatile("cp.async.cg.shared.global [%0], [%1], 16;" \
                 :: "r"(dst), "l"(src) : "memory")
#define CP_COMMIT() asm volatile("cp.async.commit_group;" ::: "memory")
#define CP_WAIT(n)  asm volatile("cp.async.wait_group %0;" :: "n"(n) : "memory")

#define LDSM_X4(r, addr) \
    asm volatile("ldmatrix.sync.aligned.m8n8.x4.shared.b16 {%0,%1,%2,%3}, [%4];" \
        : "=r"((r)[0]), "=r"((r)[1]), "=r"((r)[2]), "=r"((r)[3]) : "r"(addr))

#define MMA_BF16(c, a, b0, b1) \
    asm volatile("mma.sync.aligned.m16n8k16.row.col.f32.bf16.bf16.f32 " \
        "{%0,%1,%2,%3}, {%4,%5,%6,%7}, {%8,%9}, {%0,%1,%2,%3};" \
        : "+f"((c)[0]), "+f"((c)[1]), "+f"((c)[2]), "+f"((c)[3]) \
        : "r"((a)[0]), "r"((a)[1]), "r"((a)[2]), "r"((a)[3]), "r"(b0), "r"(b1))

// ---------------------------------------------------------------------------
// fp32 -> bf16 hi/lo split helpers
// ---------------------------------------------------------------------------
__device__ __forceinline__ void split1(float x, __nv_bfloat16& h, __nv_bfloat16& l) {
    h = __float2bfloat16_rn(x);
    l = __float2bfloat16_rn(x - __bfloat162float(h));
}
__device__ __forceinline__ void split_store4(__nv_bfloat16* hi, __nv_bfloat16* lo,
                                             size_t idx, float4 y) {
    __nv_bfloat16 h0, h1, h2, h3, l0, l1, l2, l3;
    split1(y.x, h0, l0); split1(y.y, h1, l1);
    split1(y.z, h2, l2); split1(y.w, h3, l3);
    ushort4 hv = make_ushort4(__bfloat16_as_ushort(h0), __bfloat16_as_ushort(h1),
                              __bfloat16_as_ushort(h2), __bfloat16_as_ushort(h3));
    ushort4 lv = make_ushort4(__bfloat16_as_ushort(l0), __bfloat16_as_ushort(l1),
                              __bfloat16_as_ushort(l2), __bfloat16_as_ushort(l3));
    *reinterpret_cast<ushort4*>(hi + idx) = hv;
    *reinterpret_cast<ushort4*>(lo + idx) = lv;
}

// ---------------------------------------------------------------------------
// Weight transpose + split: in [K,N] fp32 -> out [N,K] bf16 hi/lo
// ---------------------------------------------------------------------------
__global__ __launch_bounds__(256) void transpose_split_kernel(
    const float* __restrict__ in, __nv_bfloat16* __restrict__ ohi,
    __nv_bfloat16* __restrict__ olo, int K, int N)
{
    __shared__ float t[32][33];
    int n0 = blockIdx.x * 32, k0 = blockIdx.y * 32;
    int tx = threadIdx.x, ty = threadIdx.y;  // block (32, 8)
    #pragma unroll
    for (int j = 0; j < 4; j++)
        t[ty + 8 * j][tx] = in[(size_t)(k0 + ty + 8 * j) * N + n0 + tx];
    __syncthreads();
    #pragma unroll
    for (int j = 0; j < 4; j++) {
        float v = t[tx][ty + 8 * j];
        size_t o = (size_t)(n0 + ty + 8 * j) * K + k0 + tx;
        __nv_bfloat16 h, l;
        split1(v, h, l);
        ohi[o] = h; olo[o] = l;
    }
}

// ---------------------------------------------------------------------------
// RMSNorm with split bf16 output
// ---------------------------------------------------------------------------
__global__ __launch_bounds__(256) void rmsnorm_split_kernel(
    const float* __restrict__ X, const float* __restrict__ W,
    __nv_bfloat16* __restrict__ Yhi, __nv_bfloat16* __restrict__ Ylo)
{
    int row = blockIdx.x;
    const float4* x4 = (const float4*)(X + (size_t)row * D);
    const float4* w4 = (const float4*)W;

    float ss = 0.f;
    #pragma unroll 2
    for (int i = threadIdx.x; i < D / 4; i += 256) {
        float4 v = x4[i];
        ss += v.x * v.x + v.y * v.y + v.z * v.z + v.w * v.w;
    }
    #pragma unroll
    for (int o = 16; o; o >>= 1) ss += __shfl_xor_sync(0xffffffffu, ss, o);
    __shared__ float red[8];
    __shared__ float s_inv;
    if ((threadIdx.x & 31) == 0) red[threadIdx.x >> 5] = ss;
    __syncthreads();
    if (threadIdx.x == 0) {
        float t = red[0] + red[1] + red[2] + red[3] + red[4] + red[5] + red[6] + red[7];
        s_inv = rsqrtf(t / (float)D + EPS);
    }
    __syncthreads();
    float inv = s_inv;
    #pragma unroll 2
    for (int i = threadIdx.x; i < D / 4; i += 256) {
        float4 v = x4[i];
        float4 w = w4[i];
        float4 y = make_float4(w.x * (v.x * inv), w.y * (v.y * inv),
                               w.z * (v.z * inv), w.w * (v.w * inv));
        split_store4(Yhi, Ylo, (size_t)row * D + i * 4, y);
    }
}

// ---------------------------------------------------------------------------
// Elementwise split (fp32 -> bf16 hi/lo)
// ---------------------------------------------------------------------------
__global__ __launch_bounds__(256) void split_kernel(
    const float* __restrict__ X, __nv_bfloat16* __restrict__ hi,
    __nv_bfloat16* __restrict__ lo)
{
    size_t i = ((size_t)blockIdx.x * blockDim.x + threadIdx.x) * 4;
    float4 v = *reinterpret_cast<const float4*>(X + i);
    split_store4(hi, lo, i, v);
}

// ---------------------------------------------------------------------------
// SiLU(h1)*h3 from packed h13 [S, 16384]; split bf16 gate output [S, 8192]
// grid: (FFI/1024, S), block 256
// ---------------------------------------------------------------------------
__global__ __launch_bounds__(256) void silu_mul_split_kernel(
    const float* __restrict__ H13, __nv_bfloat16* __restrict__ hi,
    __nv_bfloat16* __restrict__ lo)
{
    int s = blockIdx.y;
    int j = (blockIdx.x * 256 + threadIdx.x) * 4;
    const float* row = H13 + (size_t)s * W13N;
    float4 a = *reinterpret_cast<const float4*>(row + j);
    float4 b = *reinterpret_cast<const float4*>(row + FFI + j);
    float4 r;
    r.x = (a.x / (1.f + __expf(-a.x))) * b.x;
    r.y = (a.y / (1.f + __expf(-a.y))) * b.y;
    r.z = (a.z / (1.f + __expf(-a.z))) * b.z;
    r.w = (a.w / (1.f + __expf(-a.w))) * b.w;
    split_store4(hi, lo, (size_t)s * FFI + j, r);
}

// ---------------------------------------------------------------------------
// HMMA bf16x3 GEMM v2: C[M,N] = A[M,K] @ B^T[N,K] (+ optional residual R)
// Block tile 128x256, BK=32, 8 warps (2x4), warp tile 64x64, 3-stage cp.async.
// SMEM rows padded to 40 bf16 (80 B) -> conflict-free ldmatrix.
// ---------------------------------------------------------------------------
constexpr int ROWP   = 40;                 // padded row, bf16 units
constexpr int A_TILE = 128 * ROWP * 2;     // 10240 B
constexpr int B_TILE = 256 * ROWP * 2;     // 20480 B
constexpr int STAGE  = 2 * A_TILE + 2 * B_TILE;  // 61440 B
constexpr int GEMM_SMEM = 3 * STAGE;       // 184320 B

__global__ __launch_bounds__(256, 1) void gemm3_kernel(
    const __nv_bfloat16* __restrict__ Ahi, const __nv_bfloat16* __restrict__ Alo,
    const __nv_bfloat16* __restrict__ Bhi, const __nv_bfloat16* __restrict__ Blo,
    const float* __restrict__ R, float* __restrict__ C, int N, int K)
{
    extern __shared__ __align__(1024) char smem[];
    const uint32_t sb = smem_u32(smem);
    const int tid = threadIdx.x;
    const int warp = tid >> 5, lane = tid & 31;
    const int wm = warp >> 2, wn = warp & 3;         // 2 x 4 warp grid
    const int m0 = blockIdx.y * 128, n0 = blockIdx.x * 256;

    auto load_stage = [&](int st, int k0) {
        const uint32_t base = sb + st * STAGE;
        #pragma unroll
        for (int i = 0; i < 4; i++) {                 // A: 1024 chunks (hi|lo)
            int ch = tid + (i << 8);
            int sp = ch >> 9, row = (ch >> 2) & 127, c = ch & 3;
            const __nv_bfloat16* src = sp ? Alo : Ahi;
            CP_ASYNC16(base + sp * A_TILE + row * 80 + c * 16,
                       src + (size_t)(m0 + row) * K + k0 + c * 8);
        }
        #pragma unroll
        for (int i = 0; i < 8; i++) {                 // B: 2048 chunks (hi|lo)
            int ch = tid + (i << 8);
            int sp = ch >> 10, row = (ch >> 2) & 255, c = ch & 3;
            const __nv_bfloat16* src = sp ? Blo : Bhi;
            CP_ASYNC16(base + 2 * A_TILE + sp * B_TILE + row * 80 + c * 16,
                       src + (size_t)(n0 + row) * K + k0 + c * 8);
        }
    };

    float c[4][8][4];
    #pragma unroll
    for (int i = 0; i < 4; i++)
        #pragma unroll
        for (int j = 0; j < 8; j++)
            #pragma unroll
            for (int q = 0; q < 4; q++) c[i][j][q] = 0.f;

    const int a_row = wm * 64 + (lane & 15);
    const int a_kad = (lane >> 4) << 3;
    const int b_row = wn * 64 + (lane & 7) + ((lane & 16) >> 1);
    const int b_kad = (lane & 8);

    const int nc = K >> 5;
    load_stage(0, 0);
    CP_COMMIT();
    load_stage(1, 32);
    CP_COMMIT();

    for (int ci = 0; ci < nc; ci++) {
        if (ci == nc - 1) { CP_WAIT(0); } else { CP_WAIT(1); }
        __syncthreads();
        if (ci + 2 < nc) { load_stage((ci + 2) % 3, (ci + 2) << 5); CP_COMMIT(); }

        const uint32_t base = sb + (ci % 3) * STAGE;
        const uint32_t aH = base, aL = base + A_TILE;
        const uint32_t bH = base + 2 * A_TILE, bL = bH + B_TILE;

        #pragma unroll
        for (int kk = 0; kk < 32; kk += 16) {
            uint32_t ah[4][4], bh[4][4], bl[4][4];
            const uint32_t akoff = (uint32_t)((kk + a_kad) * 2);
            const uint32_t bkoff = (uint32_t)((kk + b_kad) * 2);
            #pragma unroll
            for (int mi = 0; mi < 4; mi++)
                LDSM_X4(ah[mi], aH + (a_row + mi * 16) * 80 + akoff);
            #pragma unroll
            for (int nj = 0; nj < 4; nj++) {
                LDSM_X4(bh[nj], bH + (b_row + nj * 16) * 80 + bkoff);
                LDSM_X4(bl[nj], bL + (b_row + nj * 16) * 80 + bkoff);
            }
            // pass 1: Ahi*Bhi, pass 2: Ahi*Blo
            #pragma unroll
            for (int mi = 0; mi < 4; mi++)
                #pragma unroll
                for (int nj = 0; nj < 4; nj++)
                    #pragma unroll
                    for (int hf = 0; hf < 2; hf++) {
                        MMA_BF16(c[mi][nj * 2 + hf], ah[mi],
                                 bh[nj][hf * 2], bh[nj][hf * 2 + 1]);
                        MMA_BF16(c[mi][nj * 2 + hf], ah[mi],
                                 bl[nj][hf * 2], bl[nj][hf * 2 + 1]);
                    }
            // pass 3: Alo*Bhi
            uint32_t al[4][4];
            #pragma unroll
            for (int mi = 0; mi < 4; mi++)
                LDSM_X4(al[mi], aL + (a_row + mi * 16) * 80 + akoff);
            #pragma unroll
            for (int mi = 0; mi < 4; mi++)
                #pragma unroll
                for (int nj = 0; nj < 4; nj++)
                    #pragma unroll
                    for (int hf = 0; hf < 2; hf++)
                        MMA_BF16(c[mi][nj * 2 + hf], al[mi],
                                 bh[nj][hf * 2], bh[nj][hf * 2 + 1]);
        }
        __syncthreads();
    }

    // epilogue
    const int er = m0 + wm * 64 + (lane >> 2);
    const int ec = n0 + wn * 64 + (lane & 3) * 2;
    #pragma unroll
    for (int mi = 0; mi < 4; mi++) {
        #pragma unroll
        for (int ni = 0; ni < 8; ni++) {
            int row = er + mi * 16;
            int col = ec + ni * 8;
            float2 v0 = make_float2(c[mi][ni][0], c[mi][ni][1]);
            float2 v1 = make_float2(c[mi][ni][2], c[mi][ni][3]);
            if (R) {
                float2 t0 = *(const float2*)(R + (size_t)row * N + col);
                float2 t1 = *(const float2*)(R + (size_t)(row + 8) * N + col);
                v0.x += t0.x; v0.y += t0.y;
                v1.x += t1.x; v1.y += t1.y;
            }
            *(float2*)(C + (size_t)row * N + col) = v0;
            *(float2*)(C + (size_t)(row + 8) * N + col) = v1;
        }
    }
}

// ---------------------------------------------------------------------------
// RoPE on packed QKV [S, 6144] (Q at col 0, K at col 2048), duplicated-half
// ---------------------------------------------------------------------------
__global__ __launch_bounds__(256) void rope_kernel(
    float* __restrict__ QKV,
    const float* __restrict__ cosb, const float* __restrict__ sinb)
{
    int idx = blockIdx.x * blockDim.x + threadIdx.x;
    int d = idx & 63;
    int h = (idx >> 6) & (H - 1);
    int s = idx >> 10;
    size_t base = (size_t)s * QKVN + (size_t)h * HD;
    float c = cosb[s * HD + d];
    float sn = sinb[s * HD + d];

    float q0 = QKV[base + d], q1 = QKV[base + d + 64];
    QKV[base + d]      = q0 * c - q1 * sn;
    QKV[base + d + 64] = q1 * c + q0 * sn;

    size_t kb = base + D;
    float k0 = QKV[kb + d], k1 = QKV[kb + d + 64];
    QKV[kb + d]      = k0 * c - k1 * sn;
    QKV[kb + d + 64] = k1 * c + k0 * sn;
}

// ---------------------------------------------------------------------------
// Causal attention on packed QKV: block = (head, 16 queries), SMEM K/V tiles
// ---------------------------------------------------------------------------
#define AQ 16
__global__ __launch_bounds__(512) void attn_kernel(
    const float* __restrict__ QKV, float* __restrict__ O)
{
    __shared__ float sK[32][128];
    __shared__ float sV[32][128];

    const int tid = threadIdx.x;
    const int warp = tid >> 5, lane = tid & 31;
    const int qr = blockIdx.x * AQ + warp;
    const int h = blockIdx.y;
    const int qmax = blockIdx.x * AQ + AQ - 1;
    const size_t hbase = (size_t)h * HD;
    const size_t loff = hbase + (size_t)lane * 4;

    float4 q4 = *(const float4*)(QKV + (size_t)qr * QKVN + loff);
    float m = -1e30f, l = 0.f;
    float ax = 0.f, ay = 0.f, az = 0.f, aw = 0.f;
    const float scale = 0.08838834764831845f;

    for (int t0 = 0; t0 <= qmax; t0 += 32) {
        __syncthreads();
        #pragma unroll
        for (int i = 0; i < 2; i++) {
            int el = tid + i * 512;
            int row = el >> 5;
            int c4 = (el & 31) * 4;
            int gr = t0 + row;
            if (gr < S) {
                const float* rp = QKV + (size_t)gr * QKVN + hbase + c4;
                *(float4*)(&sK[row][c4]) = *(const float4*)(rp + D);      // K
                *(float4*)(&sV[row][c4]) = *(const float4*)(rp + 2 * D);  // V
            }
        }
        __syncthreads();

        int krel = qr - t0;
        if (krel < 0) continue;
        int kend = krel < 31 ? krel : 31;
        #pragma unroll 2
        for (int kk = 0; kk <= kend; kk++) {
            float4 k4 = *(const float4*)(&sK[kk][lane * 4]);
            float s = q4.x * k4.x + q4.y * k4.y + q4.z * k4.z + q4.w * k4.w;
            #pragma unroll
            for (int o = 16; o; o >>= 1) s += __shfl_xor_sync(0xffffffffu, s, o);
            s *= scale;
            float nm = fmaxf(m, s);
            float f = __expf(m - nm);
            float p = __expf(s - nm);
            float4 v4 = *(const float4*)(&sV[kk][lane * 4]);
            l = l * f + p;
            ax = ax * f + p * v4.x;
            ay = ay * f + p * v4.y;
            az = az * f + p * v4.z;
            aw = aw * f + p * v4.w;
            m = nm;
        }
    }
    float rl = 1.f / l;
    *(float4*)(O + (size_t)qr * D + loff) = make_float4(ax * rl, ay * rl, az * rl, aw * rl);
}

// ---------------------------------------------------------------------------
// Launch
// ---------------------------------------------------------------------------
extern "C" void kernel_launch(void* const* d_in, const int* in_sizes, int n_in,
                              void* d_out, int out_size)
{
    const float* x    = (const float*)d_in[0];
    const float* fcos = (const float*)d_in[2];
    const float* fsin = (const float*)d_in[3];
    const float* wq   = (const float*)d_in[4];
    const float* wk   = (const float*)d_in[5];
    const float* wv   = (const float*)d_in[6];
    const float* wo   = (const float*)d_in[7];
    const float* w1   = (const float*)d_in[8];
    const float* w2   = (const float*)d_in[9];
    const float* w3   = (const float*)d_in[10];
    const float* anw  = (const float*)d_in[11];
    const float* fnw  = (const float*)d_in[12];
    float* out = (float*)d_out;

    float *qkv, *ao, *x1, *h13;
    __nv_bfloat16 *nxh, *nxl, *aoh, *aol, *gh, *gl;
    __nv_bfloat16 *wqkvh, *wqkvl, *woh, *wol, *w13h, *w13l, *w2h, *w2l;

    cudaGetSymbolAddress((void**)&qkv, g_qkv);
    cudaGetSymbolAddress((void**)&ao, g_ao);
    cudaGetSymbolAddress((void**)&x1, g_x1);
    cudaGetSymbolAddress((void**)&h13, g_h13);
    cudaGetSymbolAddress((void**)&nxh, g_nx_hi);
    cudaGetSymbolAddress((void**)&nxl, g_nx_lo);
    cudaGetSymbolAddress((void**)&aoh, g_ao_hi);
    cudaGetSymbolAddress((void**)&aol, g_ao_lo);
    cudaGetSymbolAddress((void**)&gh, g_g_hi);
    cudaGetSymbolAddress((void**)&gl, g_g_lo);
    cudaGetSymbolAddress((void**)&wqkvh, g_wqkvT_hi);
    cudaGetSymbolAddress((void**)&wqkvl, g_wqkvT_lo);
    cudaGetSymbolAddress((void**)&woh, g_woT_hi);
    cudaGetSymbolAddress((void**)&wol, g_woT_lo);
    cudaGetSymbolAddress((void**)&w13h, g_w13T_hi);
    cudaGetSymbolAddress((void**)&w13l, g_w13T_lo);
    cudaGetSymbolAddress((void**)&w2h, g_w2T_hi);
    cudaGetSymbolAddress((void**)&w2l, g_w2T_lo);

    cudaFuncSetAttribute(gemm3_kernel, cudaFuncAttributeMaxDynamicSharedMemorySize,
                         GEMM_SMEM);

    dim3 tb(32, 8);
    // packed transposed weights: wqkvT rows = [wq | wk | wv], w13T rows = [w1 | w3]
    transpose_split_kernel<<<dim3(D / 32, D / 32), tb>>>(wq, wqkvh, wqkvl, D, D);
    transpose_split_kernel<<<dim3(D / 32, D / 32), tb>>>(
        wk, wqkvh + (size_t)D * D, wqkvl + (size_t)D * D, D, D);
    transpose_split_kernel<<<dim3(D / 32, D / 32), tb>>>(
        wv, wqkvh + (size_t)2 * D * D, wqkvl + (size_t)2 * D * D, D, D);
    transpose_split_kernel<<<dim3(D / 32, D / 32), tb>>>(wo, woh, wol, D, D);
    transpose_split_kernel<<<dim3(FFI / 32, D / 32), tb>>>(w1, w13h, w13l, D, FFI);
    transpose_split_kernel<<<dim3(FFI / 32, D / 32), tb>>>(
        w3, w13h + (size_t)FFI * D, w13l + (size_t)FFI * D, D, FFI);
    transpose_split_kernel<<<dim3(D / 32, FFI / 32), tb>>>(w2, w2h, w2l, FFI, D);

    // attention sub-block
    rmsnorm_split_kernel<<<S, 256>>>(x, anw, nxh, nxl);
    gemm3_kernel<<<dim3(QKVN / 256, S / 128), 256, GEMM_SMEM>>>(
        nxh, nxl, wqkvh, wqkvl, nullptr, qkv, QKVN, D);
    rope_kernel<<<(S * H * 64) / 256, 256>>>(qkv, fcos, fsin);
    attn_kernel<<<dim3(S / AQ, H), 512>>>(qkv, ao);
    split_kernel<<<(S * D / 4) / 256, 256>>>(ao, aoh, aol);
    gemm3_kernel<<<dim3(D / 256, S / 128), 256, GEMM_SMEM>>>(
        aoh, aol, woh, wol, x, x1, D, D);

    // ffn sub-block
    rmsnorm_split_kernel<<<S, 256>>>(x1, fnw, nxh, nxl);
    gemm3_kernel<<<dim3(W13N / 256, S / 128), 256, GEMM_SMEM>>>(
        nxh, nxl, w13h, w13l, nullptr, h13, W13N, D);
    silu_mul_split_kernel<<<dim3(FFI / 1024, S), 256>>>(h13, gh, gl);
    gemm3_kernel<<<dim3(D / 256, S / 128), 256, GEMM_SMEM>>>(
        gh, gl, w2h, w2l, x1, out, D, FFI);
}